// round 1
// baseline (speedup 1.0000x reference)
#include <cuda_runtime.h>
#include <math.h>

#define D_MODEL   2048
#define NUM_HEADS 16
#define HEAD_DIM  128
#define KV_DIM    512
#define QKV_N     3072
#define BATCHN    2
#define SEQ       2048
#define M_TOT     4096

// Scratch (allocation-free rule: __device__ globals)
__device__ float g_qkv[(size_t)M_TOT * QKV_N];   // ~50 MB
__device__ float g_att[(size_t)M_TOT * D_MODEL]; // ~33 MB

// ---------------------------------------------------------------------------
// SGEMM: C[M,N] = A[M,K] @ B[K,N], all row-major fp32.
// 128x128 block tile, BK=16, 256 threads, 8x8 per-thread micro-tile.
// ---------------------------------------------------------------------------
__global__ void __launch_bounds__(256) sgemm128(const float* __restrict__ A,
                                                const float* __restrict__ B,
                                                float* __restrict__ C,
                                                int M, int N, int K)
{
    __shared__ float As[16][128];  // transposed A tile: As[k][m]
    __shared__ float Bs[16][128];  // Bs[k][n]
    const int tid = threadIdx.x;
    const int ty = tid >> 4, tx = tid & 15;
    const int brow = blockIdx.y * 128;
    const int bcol = blockIdx.x * 128;

    float acc[8][8];
#pragma unroll
    for (int i = 0; i < 8; i++)
#pragma unroll
        for (int j = 0; j < 8; j++) acc[i][j] = 0.f;

    const float* Ap = A + (size_t)brow * K;
    const float* Bp = B + bcol;

    for (int k0 = 0; k0 < K; k0 += 16) {
#pragma unroll
        for (int i = 0; i < 2; i++) {
            int idx = tid + i * 256;
            int r = idx >> 2, c4 = idx & 3;
            float4 v = *(const float4*)(Ap + (size_t)r * K + k0 + c4 * 4);
            As[c4 * 4 + 0][r] = v.x;
            As[c4 * 4 + 1][r] = v.y;
            As[c4 * 4 + 2][r] = v.z;
            As[c4 * 4 + 3][r] = v.w;
        }
#pragma unroll
        for (int i = 0; i < 2; i++) {
            int idx = tid + i * 256;
            int r = idx >> 5, c4 = idx & 31;
            *(float4*)(&Bs[r][c4 * 4]) =
                *(const float4*)(Bp + (size_t)(k0 + r) * N + c4 * 4);
        }
        __syncthreads();
#pragma unroll
        for (int kk = 0; kk < 16; kk++) {
            float4 a0 = *(const float4*)(&As[kk][ty * 8]);
            float4 a1 = *(const float4*)(&As[kk][ty * 8 + 4]);
            float4 b0 = *(const float4*)(&Bs[kk][tx * 8]);
            float4 b1 = *(const float4*)(&Bs[kk][tx * 8 + 4]);
            float a[8] = {a0.x, a0.y, a0.z, a0.w, a1.x, a1.y, a1.z, a1.w};
            float bb[8] = {b0.x, b0.y, b0.z, b0.w, b1.x, b1.y, b1.z, b1.w};
#pragma unroll
            for (int i = 0; i < 8; i++)
#pragma unroll
                for (int j = 0; j < 8; j++)
                    acc[i][j] = fmaf(a[i], bb[j], acc[i][j]);
        }
        __syncthreads();
    }

#pragma unroll
    for (int i = 0; i < 8; i++) {
        size_t r = (size_t)(brow + ty * 8 + i);
        float* cp = C + r * N + bcol + tx * 8;
        *(float4*)cp       = make_float4(acc[i][0], acc[i][1], acc[i][2], acc[i][3]);
        *(float4*)(cp + 4) = make_float4(acc[i][4], acc[i][5], acc[i][6], acc[i][7]);
    }
}

// ---------------------------------------------------------------------------
// RoPE in-place on g_qkv for Q (16 heads) and K (4 heads).
// ---------------------------------------------------------------------------
__global__ void rope_kernel(const float* __restrict__ sinp,
                            const float* __restrict__ cosp)
{
    int i = blockIdx.x * blockDim.x + threadIdx.x;  // over M_TOT*20*64
    int d  = i & 63;
    int hh = (i >> 6) % 20;
    int m  = i / (64 * 20);
    int t  = m & (SEQ - 1);
    int col = (hh < 16) ? hh * 128 : D_MODEL + (hh - 16) * 128;
    float s = sinp[t * 64 + d];
    float c = cosp[t * 64 + d];
    float* p = g_qkv + (size_t)m * QKV_N + col;
    float x1 = p[d], x2 = p[d + 64];
    p[d]      = x1 * c - x2 * s;
    p[d + 64] = x2 * c + x1 * s;
}

// ---------------------------------------------------------------------------
// Flash attention with causal + document mask.
// One block per (batch b, head h, 64-query tile). 256 threads.
// Scores: 16x16 thread grid, 4x4 per thread (Q,K transposed in smem).
// PV:     4 rows x 8 cols per thread.
// Doc-sorted tile skip: key tile fully earlier-doc -> skip.
// ---------------------------------------------------------------------------
#define TQ 64
#define TK 64
// smem floats: qst 128*65=8320 | kv 8448 (max of kst 8320, vs 64*132) | ss 64*65=4160
// | rowm/rowl/corr 192 | qdoc/kdoc 128 ints
#define SM_QST 0
#define SM_KV  8320
#define SM_SS  (8320 + 8448)
#define SM_RM  (SM_SS + 64 * 65)
#define SM_RL  (SM_RM + 64)
#define SM_CO  (SM_RL + 64)
#define SM_FLOATS (SM_CO + 64)
#define ATTN_SMEM_BYTES (SM_FLOATS * 4 + 128 * 4)

__global__ void __launch_bounds__(256) attn_kernel(const int* __restrict__ doc_ids)
{
    extern __shared__ char smem_raw[];
    float* sm   = (float*)smem_raw;
    float* qst  = sm + SM_QST;   // [128][65] transposed Q
    float* kst  = sm + SM_KV;    // [128][65] transposed K  (reused as vs[64][132])
    float* vs   = kst;
    float* ss   = sm + SM_SS;    // [64][65]
    float* rowm = sm + SM_RM;
    float* rowl = sm + SM_RL;
    float* corr = sm + SM_CO;
    int*   qdoc = (int*)(sm + SM_FLOATS);
    int*   kdoc = qdoc + 64;

    const int qt  = blockIdx.x;
    const int h   = blockIdx.y;
    const int b   = blockIdx.z;
    const int g   = h >> 2;          // kv head
    const int tid = threadIdx.x;
    const int ty  = tid >> 4, tx = tid & 15;
    const int t0  = qt * TQ;
    const size_t base_m = (size_t)b * SEQ;

    // Load Q tile transposed
    const float* qb = g_qkv + (base_m + t0) * QKV_N + h * HEAD_DIM;
#pragma unroll
    for (int i = 0; i < 8; i++) {
        int idx = tid + i * 256;
        int r = idx >> 5, c4 = idx & 31;
        float4 v = *(const float4*)(qb + (size_t)r * QKV_N + c4 * 4);
        qst[(c4 * 4 + 0) * 65 + r] = v.x;
        qst[(c4 * 4 + 1) * 65 + r] = v.y;
        qst[(c4 * 4 + 2) * 65 + r] = v.z;
        qst[(c4 * 4 + 3) * 65 + r] = v.w;
    }
    if (tid < 64) {
        qdoc[tid] = doc_ids[b * SEQ + t0 + tid];
        rowm[tid] = -1e30f;
        rowl[tid] = 0.f;
    }
    float acc[4][8];
#pragma unroll
    for (int i = 0; i < 4; i++)
#pragma unroll
        for (int j = 0; j < 8; j++) acc[i][j] = 0.f;

    __syncthreads();
    const int dq_min = qdoc[0];

    const float scale = 0.08838834764831845f;  // 1/sqrt(128)

    for (int kt = 0; kt <= qt; kt++) {
        if (tid < 64) kdoc[tid] = doc_ids[b * SEQ + kt * TK + tid];
        __syncthreads();
        if (kdoc[63] < dq_min) continue;  // whole key tile in earlier docs

        // Load K tile transposed (into kst)
        const float* kb = g_qkv + (base_m + kt * TK) * QKV_N + D_MODEL + g * HEAD_DIM;
#pragma unroll
        for (int i = 0; i < 8; i++) {
            int idx = tid + i * 256;
            int r = idx >> 5, c4 = idx & 31;
            float4 v = *(const float4*)(kb + (size_t)r * QKV_N + c4 * 4);
            kst[(c4 * 4 + 0) * 65 + r] = v.x;
            kst[(c4 * 4 + 1) * 65 + r] = v.y;
            kst[(c4 * 4 + 2) * 65 + r] = v.z;
            kst[(c4 * 4 + 3) * 65 + r] = v.w;
        }
        __syncthreads();

        // Scores: 4x4 per thread over K dim 128
        float sc[4][4];
#pragma unroll
        for (int i = 0; i < 4; i++)
#pragma unroll
            for (int j = 0; j < 4; j++) sc[i][j] = 0.f;

#pragma unroll 4
        for (int kk = 0; kk < 128; kk++) {
            float a[4], bb[4];
#pragma unroll
            for (int i = 0; i < 4; i++) a[i] = qst[kk * 65 + ty * 4 + i];
#pragma unroll
            for (int j = 0; j < 4; j++) bb[j] = kst[kk * 65 + tx * 4 + j];
#pragma unroll
            for (int i = 0; i < 4; i++)
#pragma unroll
                for (int j = 0; j < 4; j++)
                    sc[i][j] = fmaf(a[i], bb[j], sc[i][j]);
        }

        // Scale + mask, write to ss
#pragma unroll
        for (int i = 0; i < 4; i++) {
            int r  = ty * 4 + i;
            int qi = t0 + r;
            int qd = qdoc[r];
#pragma unroll
            for (int j = 0; j < 4; j++) {
                int c  = tx * 4 + j;
                int kj = kt * TK + c;
                float v = sc[i][j] * scale;
                if (kj > qi || qd != kdoc[c]) v = -1e30f;
                ss[r * 65 + c] = v;
            }
        }
        __syncthreads();  // ss ready; kst reads done -> kv buffer reusable

        // Load V tile row-major into vs (overwrites kst region)
        const float* vb = g_qkv + (base_m + kt * TK) * QKV_N + D_MODEL + KV_DIM + g * HEAD_DIM;
#pragma unroll
        for (int i = 0; i < 8; i++) {
            int idx = tid + i * 256;
            int r = idx >> 5, c4 = idx & 31;
            *(float4*)(&vs[r * 132 + c4 * 4]) =
                *(const float4*)(vb + (size_t)r * QKV_N + c4 * 4);
        }

        // Online softmax per row (64 threads)
        if (tid < 64) {
            int r = tid;
            float mold = rowm[r];
            float mx = mold;
#pragma unroll 8
            for (int c = 0; c < 64; c++) mx = fmaxf(mx, ss[r * 65 + c]);
            float cf = __expf(mold - mx);   // mold==mx==-1e30 -> 1, l stays 0: ok
            float l = rowl[r] * cf;
#pragma unroll 8
            for (int c = 0; c < 64; c++) {
                float sv = ss[r * 65 + c];
                float e = (sv > -1e29f) ? __expf(sv - mx) : 0.f;
                ss[r * 65 + c] = e;
                l += e;
            }
            rowm[r] = mx;
            rowl[r] = l;
            corr[r] = cf;
        }
        __syncthreads();

        // Rescale accumulator
#pragma unroll
        for (int i = 0; i < 4; i++) {
            float cf = corr[ty * 4 + i];
#pragma unroll
            for (int j = 0; j < 8; j++) acc[i][j] *= cf;
        }

        // PV: acc[4][8] += P[4][64] @ V[64][8]
#pragma unroll 2
        for (int kk = 0; kk < 64; kk++) {
            float p[4];
#pragma unroll
            for (int i = 0; i < 4; i++) p[i] = ss[(ty * 4 + i) * 65 + kk];
            float4 v0 = *(const float4*)(&vs[kk * 132 + tx * 8]);
            float4 v1 = *(const float4*)(&vs[kk * 132 + tx * 8 + 4]);
#pragma unroll
            for (int i = 0; i < 4; i++) {
                acc[i][0] = fmaf(p[i], v0.x, acc[i][0]);
                acc[i][1] = fmaf(p[i], v0.y, acc[i][1]);
                acc[i][2] = fmaf(p[i], v0.z, acc[i][2]);
                acc[i][3] = fmaf(p[i], v0.w, acc[i][3]);
                acc[i][4] = fmaf(p[i], v1.x, acc[i][4]);
                acc[i][5] = fmaf(p[i], v1.y, acc[i][5]);
                acc[i][6] = fmaf(p[i], v1.z, acc[i][6]);
                acc[i][7] = fmaf(p[i], v1.w, acc[i][7]);
            }
        }
        __syncthreads();  // protect vs/ss before next tile's overwrites
    }

    // Epilogue: divide by l, write to g_att
#pragma unroll
    for (int i = 0; i < 4; i++) {
        int r = ty * 4 + i;
        float inv = 1.f / rowl[r];
        float* op = g_att + (base_m + t0 + r) * D_MODEL + h * HEAD_DIM + tx * 8;
        *(float4*)op       = make_float4(acc[i][0] * inv, acc[i][1] * inv,
                                         acc[i][2] * inv, acc[i][3] * inv);
        *(float4*)(op + 4) = make_float4(acc[i][4] * inv, acc[i][5] * inv,
                                         acc[i][6] * inv, acc[i][7] * inv);
    }
}

// ---------------------------------------------------------------------------
extern "C" void kernel_launch(void* const* d_in, const int* in_sizes, int n_in,
                              void* d_out, int out_size)
{
    const float* x    = (const float*)d_in[0];
    const float* sinp = (const float*)d_in[1];
    const float* cosp = (const float*)d_in[2];
    const int*   doc  = (const int*)d_in[3];
    const float* Wqkv = (const float*)d_in[4];
    const float* Wo   = (const float*)d_in[5];
    float* out = (float*)d_out;

    float *qkv_ptr, *att_ptr;
    cudaGetSymbolAddress((void**)&qkv_ptr, g_qkv);
    cudaGetSymbolAddress((void**)&att_ptr, g_att);

    // 1) QKV projection
    dim3 g1(QKV_N / 128, M_TOT / 128);
    sgemm128<<<g1, 256>>>(x, Wqkv, qkv_ptr, M_TOT, QKV_N, D_MODEL);

    // 2) RoPE (Q + K heads)
    int total = M_TOT * 20 * 64;
    rope_kernel<<<total / 256, 256>>>(sinp, cosp);

    // 3) Attention
    cudaFuncSetAttribute(attn_kernel,
                         cudaFuncAttributeMaxDynamicSharedMemorySize,
                         ATTN_SMEM_BYTES);
    dim3 ga(SEQ / TQ, NUM_HEADS, BATCHN);
    attn_kernel<<<ga, 256, ATTN_SMEM_BYTES>>>(doc);

    // 4) Output projection
    dim3 g2(D_MODEL / 128, M_TOT / 128);
    sgemm128<<<g2, 256>>>(att_ptr, Wo, out, M_TOT, D_MODEL, D_MODEL);
}

// round 5
// speedup vs baseline: 2.9572x; 2.9572x over previous
#include <cuda_runtime.h>
#include <cuda_fp16.h>
#include <cstdint>
#include <math.h>

#define D_MODEL   2048
#define NUM_HEADS 16
#define HEAD_DIM  128
#define KV_DIM    512
#define QKV_N     3072
#define BATCHN    2
#define SEQ       2048
#define M_TOT     4096

// ---------------------------------------------------------------------------
// Scratch (__device__ globals; allocation-free rule)
// ---------------------------------------------------------------------------
__device__ float g_qkv[(size_t)M_TOT * QKV_N];                       // fp32 QKV
__device__ __align__(16) __half g_Ax[(size_t)M_TOT * D_MODEL];      // x in fp16
__device__ __align__(16) __half g_Aatt[(size_t)M_TOT * D_MODEL];    // attn out fp16
__device__ __align__(16) __half g_Bqkv[(size_t)QKV_N * D_MODEL];    // W_qkv^T fp16 [N][K]
__device__ __align__(16) __half g_Bo[(size_t)D_MODEL * D_MODEL];    // W_o^T fp16 [N][K]

__device__ __forceinline__ uint32_t smem_u32(const void* p) {
    uint32_t a;
    asm("{ .reg .u64 t; cvta.to.shared.u64 t, %1; cvt.u32.u64 %0, t; }" : "=r"(a) : "l"(p));
    return a;
}

// ---------------------------------------------------------------------------
// fp16 tensor-core GEMM via mma.sync: C[M,N] = A[M,K] @ B[N,K]^T, fp32 out.
// 128x128 CTA tile, KC=32 double-buffered cp.async, 256 threads.
// Warp grid 2x4 -> warp tile 64x32. m16n8k16 fragments via ldmatrix.
// Smem rows padded to 40 halves (80B): conflict-free ldmatrix.
// ---------------------------------------------------------------------------
__global__ void __launch_bounds__(256, 2) gemm_mma(const __half* __restrict__ A,
                                                   const __half* __restrict__ B,
                                                   float* __restrict__ C,
                                                   int N, int K)
{
    __shared__ __half As[2][5120];   // [buf][128 rows * 40]
    __shared__ __half Bs[2][5120];
    const int tid = threadIdx.x;
    const int w = tid >> 5, l = tid & 31;
    const int brow = blockIdx.y * 128, bcol = blockIdx.x * 128;
    const int wm = (w >> 2) * 64, wn = (w & 3) * 32;
    const uint32_t sa0 = smem_u32(As), sb0 = smem_u32(Bs);
    const int NIT = K >> 5;

    float acc[4][4][4];
#pragma unroll
    for (int a = 0; a < 4; a++)
#pragma unroll
        for (int b = 0; b < 4; b++)
#pragma unroll
            for (int c = 0; c < 4; c++) acc[a][b][c] = 0.f;

    const int lr0 = tid >> 2, lkc = tid & 3;
    const __half* Ag = A + (size_t)brow * K;
    const __half* Bg = B + (size_t)bcol * K;

    auto LOAD = [&](int buf, int k0) {
#pragma unroll
        for (int j = 0; j < 2; j++) {
            int r = lr0 + j * 64;
            uint32_t so = (uint32_t)(buf * 5120 + r * 40 + lkc * 8) * 2;
            const __half* ga = Ag + (size_t)r * K + k0 + lkc * 8;
            const __half* gb = Bg + (size_t)r * K + k0 + lkc * 8;
            asm volatile("cp.async.cg.shared.global [%0], [%1], 16;\n"
                         :: "r"(sa0 + so), "l"(ga));
            asm volatile("cp.async.cg.shared.global [%0], [%1], 16;\n"
                         :: "r"(sb0 + so), "l"(gb));
        }
        asm volatile("cp.async.commit_group;\n" ::: "memory");
    };

    LOAD(0, 0);

    for (int i = 0; i < NIT; i++) {
        const int p = i & 1;
        if (i + 1 < NIT) {
            LOAD(p ^ 1, (i + 1) * 32);
            asm volatile("cp.async.wait_group 1;\n" ::: "memory");
        } else {
            asm volatile("cp.async.wait_group 0;\n" ::: "memory");
        }
        __syncthreads();

        // B fragments: 4 n-frags, ldmatrix.x4 covers k0..31 (both k16 steps)
        uint32_t bfr[4][4];
#pragma unroll
        for (int nf = 0; nf < 4; nf++) {
            uint32_t addr = sb0 + (uint32_t)(p * 5120 +
                            (wn + nf * 8 + (l & 7)) * 40 + (l >> 3) * 8) * 2;
            asm volatile("ldmatrix.sync.aligned.m8n8.x4.shared.b16 {%0,%1,%2,%3}, [%4];"
                         : "=r"(bfr[nf][0]), "=r"(bfr[nf][1]),
                           "=r"(bfr[nf][2]), "=r"(bfr[nf][3])
                         : "r"(addr) : "memory");
        }

#pragma unroll
        for (int s = 0; s < 2; s++) {
            uint32_t afr[4][4];
#pragma unroll
            for (int mf = 0; mf < 4; mf++) {
                int row = wm + mf * 16 + ((l >> 3) & 1) * 8 + (l & 7);
                int chunk = 2 * s + (l >> 4);
                uint32_t addr = sa0 + (uint32_t)(p * 5120 + row * 40 + chunk * 8) * 2;
                asm volatile("ldmatrix.sync.aligned.m8n8.x4.shared.b16 {%0,%1,%2,%3}, [%4];"
                             : "=r"(afr[mf][0]), "=r"(afr[mf][1]),
                               "=r"(afr[mf][2]), "=r"(afr[mf][3])
                             : "r"(addr) : "memory");
            }
#pragma unroll
            for (int mf = 0; mf < 4; mf++)
#pragma unroll
                for (int nf = 0; nf < 4; nf++) {
                    asm volatile(
                        "mma.sync.aligned.m16n8k16.row.col.f32.f16.f16.f32 "
                        "{%0,%1,%2,%3},{%4,%5,%6,%7},{%8,%9},{%0,%1,%2,%3};"
                        : "+f"(acc[mf][nf][0]), "+f"(acc[mf][nf][1]),
                          "+f"(acc[mf][nf][2]), "+f"(acc[mf][nf][3])
                        : "r"(afr[mf][0]), "r"(afr[mf][1]),
                          "r"(afr[mf][2]), "r"(afr[mf][3]),
                          "r"(bfr[nf][2 * s]), "r"(bfr[nf][2 * s + 1]));
                }
        }
        __syncthreads();
    }

    // Epilogue: c0,c1 -> (row, col), (row, col+1); c2,c3 -> (row+8, ...)
#pragma unroll
    for (int mf = 0; mf < 4; mf++) {
        int r0 = brow + wm + mf * 16 + (l >> 2);
#pragma unroll
        for (int nf = 0; nf < 4; nf++) {
            int c = bcol + wn + nf * 8 + (l & 3) * 2;
            *(float2*)(C + (size_t)r0 * N + c) =
                make_float2(acc[mf][nf][0], acc[mf][nf][1]);
            *(float2*)(C + (size_t)(r0 + 8) * N + c) =
                make_float2(acc[mf][nf][2], acc[mf][nf][3]);
        }
    }
}

// ---------------------------------------------------------------------------
// fp32 -> fp16 convert (same layout), vectorized x4
// ---------------------------------------------------------------------------
__global__ void conv_half4(const float* __restrict__ s, __half* __restrict__ d)
{
    int i = blockIdx.x * blockDim.x + threadIdx.x;
    float4 v = ((const float4*)s)[i];
    __half2 h0 = __floats2half2_rn(v.x, v.y);
    __half2 h1 = __floats2half2_rn(v.z, v.w);
    ((__half2*)d)[2 * i]     = h0;
    ((__half2*)d)[2 * i + 1] = h1;
}

// W[2048 x Ncols] fp32 -> dst[Ncols x 2048] fp16 (transpose)
__global__ void convT_half(const float* __restrict__ W,
                           __half* __restrict__ dst, int Ncols)
{
    __shared__ float t[32][33];
    int k0 = blockIdx.y * 32, n0 = blockIdx.x * 32;
    int tx = threadIdx.x, ty = threadIdx.y;          // 32 x 8
#pragma unroll
    for (int r = 0; r < 32; r += 8)
        t[ty + r][tx] = W[(size_t)(k0 + ty + r) * Ncols + n0 + tx];
    __syncthreads();
#pragma unroll
    for (int r = 0; r < 32; r += 8) {
        int n = n0 + ty + r, k = k0 + tx;
        dst[(size_t)n * D_MODEL + k] = __float2half(t[tx][ty + r]);
    }
}

// ---------------------------------------------------------------------------
// RoPE in-place on g_qkv for Q (16 heads) and K (4 heads).
// ---------------------------------------------------------------------------
__global__ void rope_kernel(const float* __restrict__ sinp,
                            const float* __restrict__ cosp)
{
    int i = blockIdx.x * blockDim.x + threadIdx.x;
    int d  = i & 63;
    int hh = (i >> 6) % 20;
    int m  = i / (64 * 20);
    int t  = m & (SEQ - 1);
    int col = (hh < 16) ? hh * 128 : D_MODEL + (hh - 16) * 128;
    float s = sinp[t * 64 + d];
    float c = cosp[t * 64 + d];
    float* p = g_qkv + (size_t)m * QKV_N + col;
    float x1 = p[d], x2 = p[d + 64];
    p[d]      = x1 * c - x2 * s;
    p[d + 64] = x2 * c + x1 * s;
}

// ---------------------------------------------------------------------------
// Flash attention with causal + document mask (SIMT, fp32).
// Epilogue writes fp16 directly into g_Aatt (A operand of O-projection).
// ---------------------------------------------------------------------------
#define TQ 64
#define TK 64
#define SM_QST 0
#define SM_KV  8320
#define SM_SS  (8320 + 8448)
#define SM_RM  (SM_SS + 64 * 65)
#define SM_RL  (SM_RM + 64)
#define SM_CO  (SM_RL + 64)
#define SM_FLOATS (SM_CO + 64)
#define ATTN_SMEM_BYTES (SM_FLOATS * 4 + 128 * 4)

__global__ void __launch_bounds__(256) attn_kernel(const int* __restrict__ doc_ids)
{
    extern __shared__ char smem_raw[];
    float* sm   = (float*)smem_raw;
    float* qst  = sm + SM_QST;
    float* kst  = sm + SM_KV;
    float* vs   = kst;
    float* ss   = sm + SM_SS;
    float* rowm = sm + SM_RM;
    float* rowl = sm + SM_RL;
    float* corr = sm + SM_CO;
    int*   qdoc = (int*)(sm + SM_FLOATS);
    int*   kdoc = qdoc + 64;

    const int qt  = blockIdx.x;
    const int h   = blockIdx.y;
    const int b   = blockIdx.z;
    const int g   = h >> 2;
    const int tid = threadIdx.x;
    const int ty  = tid >> 4, tx = tid & 15;
    const int t0  = qt * TQ;
    const size_t base_m = (size_t)b * SEQ;

    const float* qb = g_qkv + (base_m + t0) * QKV_N + h * HEAD_DIM;
#pragma unroll
    for (int i = 0; i < 8; i++) {
        int idx = tid + i * 256;
        int r = idx >> 5, c4 = idx & 31;
        float4 v = *(const float4*)(qb + (size_t)r * QKV_N + c4 * 4);
        qst[(c4 * 4 + 0) * 65 + r] = v.x;
        qst[(c4 * 4 + 1) * 65 + r] = v.y;
        qst[(c4 * 4 + 2) * 65 + r] = v.z;
        qst[(c4 * 4 + 3) * 65 + r] = v.w;
    }
    if (tid < 64) {
        qdoc[tid] = doc_ids[b * SEQ + t0 + tid];
        rowm[tid] = -1e30f;
        rowl[tid] = 0.f;
    }
    float acc[4][8];
#pragma unroll
    for (int i = 0; i < 4; i++)
#pragma unroll
        for (int j = 0; j < 8; j++) acc[i][j] = 0.f;

    __syncthreads();
    const int dq_min = qdoc[0];
    const float scale = 0.08838834764831845f;

    for (int kt = 0; kt <= qt; kt++) {
        if (tid < 64) kdoc[tid] = doc_ids[b * SEQ + kt * TK + tid];
        __syncthreads();
        if (kdoc[63] < dq_min) continue;

        const float* kb = g_qkv + (base_m + kt * TK) * QKV_N + D_MODEL + g * HEAD_DIM;
#pragma unroll
        for (int i = 0; i < 8; i++) {
            int idx = tid + i * 256;
            int r = idx >> 5, c4 = idx & 31;
            float4 v = *(const float4*)(kb + (size_t)r * QKV_N + c4 * 4);
            kst[(c4 * 4 + 0) * 65 + r] = v.x;
            kst[(c4 * 4 + 1) * 65 + r] = v.y;
            kst[(c4 * 4 + 2) * 65 + r] = v.z;
            kst[(c4 * 4 + 3) * 65 + r] = v.w;
        }
        __syncthreads();

        float sc[4][4];
#pragma unroll
        for (int i = 0; i < 4; i++)
#pragma unroll
            for (int j = 0; j < 4; j++) sc[i][j] = 0.f;

#pragma unroll 4
        for (int kk = 0; kk < 128; kk++) {
            float a[4], bb[4];
#pragma unroll
            for (int i = 0; i < 4; i++) a[i] = qst[kk * 65 + ty * 4 + i];
#pragma unroll
            for (int j = 0; j < 4; j++) bb[j] = kst[kk * 65 + tx * 4 + j];
#pragma unroll
            for (int i = 0; i < 4; i++)
#pragma unroll
                for (int j = 0; j < 4; j++)
                    sc[i][j] = fmaf(a[i], bb[j], sc[i][j]);
        }

#pragma unroll
        for (int i = 0; i < 4; i++) {
            int r  = ty * 4 + i;
            int qi = t0 + r;
            int qd = qdoc[r];
#pragma unroll
            for (int j = 0; j < 4; j++) {
                int c  = tx * 4 + j;
                int kj = kt * TK + c;
                float v = sc[i][j] * scale;
                if (kj > qi || qd != kdoc[c]) v = -1e30f;
                ss[r * 65 + c] = v;
            }
        }
        __syncthreads();

        const float* vb = g_qkv + (base_m + kt * TK) * QKV_N + D_MODEL + KV_DIM + g * HEAD_DIM;
#pragma unroll
        for (int i = 0; i < 8; i++) {
            int idx = tid + i * 256;
            int r = idx >> 5, c4 = idx & 31;
            *(float4*)(&vs[r * 132 + c4 * 4]) =
                *(const float4*)(vb + (size_t)r * QKV_N + c4 * 4);
        }

        if (tid < 64) {
            int r = tid;
            float mold = rowm[r];
            float mx = mold;
#pragma unroll 8
            for (int c = 0; c < 64; c++) mx = fmaxf(mx, ss[r * 65 + c]);
            float cf = __expf(mold - mx);
            float l = rowl[r] * cf;
#pragma unroll 8
            for (int c = 0; c < 64; c++) {
                float sv = ss[r * 65 + c];
                float e = (sv > -1e29f) ? __expf(sv - mx) : 0.f;
                ss[r * 65 + c] = e;
                l += e;
            }
            rowm[r] = mx;
            rowl[r] = l;
            corr[r] = cf;
        }
        __syncthreads();

#pragma unroll
        for (int i = 0; i < 4; i++) {
            float cf = corr[ty * 4 + i];
#pragma unroll
            for (int j = 0; j < 8; j++) acc[i][j] *= cf;
        }

#pragma unroll 2
        for (int kk = 0; kk < 64; kk++) {
            float p[4];
#pragma unroll
            for (int i = 0; i < 4; i++) p[i] = ss[(ty * 4 + i) * 65 + kk];
            float4 v0 = *(const float4*)(&vs[kk * 132 + tx * 8]);
            float4 v1 = *(const float4*)(&vs[kk * 132 + tx * 8 + 4]);
#pragma unroll
            for (int i = 0; i < 4; i++) {
                acc[i][0] = fmaf(p[i], v0.x, acc[i][0]);
                acc[i][1] = fmaf(p[i], v0.y, acc[i][1]);
                acc[i][2] = fmaf(p[i], v0.z, acc[i][2]);
                acc[i][3] = fmaf(p[i], v0.w, acc[i][3]);
                acc[i][4] = fmaf(p[i], v1.x, acc[i][4]);
                acc[i][5] = fmaf(p[i], v1.y, acc[i][5]);
                acc[i][6] = fmaf(p[i], v1.z, acc[i][6]);
                acc[i][7] = fmaf(p[i], v1.w, acc[i][7]);
            }
        }
        __syncthreads();
    }

    // Fused epilogue: out = acc / l -> fp16 into g_Aatt
#pragma unroll
    for (int i = 0; i < 4; i++) {
        int r = ty * 4 + i;
        float inv = 1.f / rowl[r];
        size_t mrow = base_m + t0 + r;
        size_t col  = (size_t)h * HEAD_DIM + tx * 8;
        __half h8[8];
#pragma unroll
        for (int j = 0; j < 8; j++)
            h8[j] = __float2half(acc[i][j] * inv);
        *(float4*)(g_Aatt + mrow * D_MODEL + col) = *(float4*)h8;
    }
}

// ---------------------------------------------------------------------------
extern "C" void kernel_launch(void* const* d_in, const int* in_sizes, int n_in,
                              void* d_out, int out_size)
{
    const float* x    = (const float*)d_in[0];
    const float* sinp = (const float*)d_in[1];
    const float* cosp = (const float*)d_in[2];
    const int*   doc  = (const int*)d_in[3];
    const float* Wqkv = (const float*)d_in[4];
    const float* Wo   = (const float*)d_in[5];
    float* out = (float*)d_out;

    float* qkv_ptr;
    __half *ax, *aatt, *bqkv, *bo;
    cudaGetSymbolAddress((void**)&qkv_ptr, g_qkv);
    cudaGetSymbolAddress((void**)&ax,   g_Ax);
    cudaGetSymbolAddress((void**)&aatt, g_Aatt);
    cudaGetSymbolAddress((void**)&bqkv, g_Bqkv);
    cudaGetSymbolAddress((void**)&bo,   g_Bo);

    cudaFuncSetAttribute(attn_kernel, cudaFuncAttributeMaxDynamicSharedMemorySize,
                         ATTN_SMEM_BYTES);

    // 1) fp16 conversions for QKV GEMM
    conv_half4<<<(M_TOT * D_MODEL / 4) / 256, 256>>>(x, ax);
    convT_half<<<dim3(QKV_N / 32, D_MODEL / 32), dim3(32, 8)>>>(Wqkv, bqkv, QKV_N);

    // 2) QKV projection (tensor cores, fp16 mma.sync)
    gemm_mma<<<dim3(QKV_N / 128, M_TOT / 128), 256>>>(ax, bqkv, qkv_ptr, QKV_N, D_MODEL);

    // 3) RoPE
    rope_kernel<<<(M_TOT * 20 * 64) / 256, 256>>>(sinp, cosp);

    // 4) Attention (epilogue emits fp16 A operand)
    attn_kernel<<<dim3(SEQ / TQ, NUM_HEADS, BATCHN), 256, ATTN_SMEM_BYTES>>>(doc);

    // 5) W_o conversion + output projection
    convT_half<<<dim3(D_MODEL / 32, D_MODEL / 32), dim3(32, 8)>>>(Wo, bo, D_MODEL);
    gemm_mma<<<dim3(D_MODEL / 128, M_TOT / 128), 256>>>(aatt, bo, out, D_MODEL, D_MODEL);
}

// round 7
// speedup vs baseline: 4.7375x; 1.6020x over previous
#include <cuda_runtime.h>
#include <cuda_fp16.h>
#include <cstdint>
#include <math.h>

#define D_MODEL   2048
#define NUM_HEADS 16
#define HEAD_DIM  128
#define KV_DIM    512
#define QKV_N     3072
#define BATCHN    2
#define SEQ       2048
#define M_TOT     4096

// ---------------------------------------------------------------------------
// Scratch (__device__ globals; allocation-free rule)
// ---------------------------------------------------------------------------
__device__ float g_qkv[(size_t)M_TOT * QKV_N];                       // fp32 QKV
__device__ __align__(16) __half g_Ax[(size_t)M_TOT * D_MODEL];       // x fp16
__device__ __align__(16) __half g_Aatt[(size_t)M_TOT * D_MODEL];     // attn out fp16
__device__ __align__(16) __half g_Bqkv[(size_t)QKV_N * D_MODEL];     // W_qkv^T fp16
__device__ __align__(16) __half g_Bo[(size_t)D_MODEL * D_MODEL];     // W_o^T fp16
__device__ __align__(16) __half g_Qh[(size_t)BATCHN * NUM_HEADS * SEQ * HEAD_DIM]; // rope'd Q
__device__ __align__(16) __half g_Kh[(size_t)BATCHN * 4 * SEQ * HEAD_DIM];         // rope'd K
__device__ __align__(16) __half g_Vt[(size_t)BATCHN * 4 * HEAD_DIM * SEQ];         // V^T

__device__ __forceinline__ uint32_t smem_u32(const void* p) {
    uint32_t a;
    asm("{ .reg .u64 t; cvta.to.shared.u64 t, %1; cvt.u32.u64 %0, t; }" : "=r"(a) : "l"(p));
    return a;
}
__device__ __forceinline__ void ldsm_x4(uint32_t* r, uint32_t addr) {
    asm volatile("ldmatrix.sync.aligned.m8n8.x4.shared.b16 {%0,%1,%2,%3}, [%4];"
                 : "=r"(r[0]), "=r"(r[1]), "=r"(r[2]), "=r"(r[3]) : "r"(addr) : "memory");
}
__device__ __forceinline__ void mma16816(float* c, const uint32_t* a,
                                         uint32_t b0, uint32_t b1) {
    asm volatile("mma.sync.aligned.m16n8k16.row.col.f32.f16.f16.f32 "
                 "{%0,%1,%2,%3},{%4,%5,%6,%7},{%8,%9},{%0,%1,%2,%3};"
                 : "+f"(c[0]), "+f"(c[1]), "+f"(c[2]), "+f"(c[3])
                 : "r"(a[0]), "r"(a[1]), "r"(a[2]), "r"(a[3]), "r"(b0), "r"(b1));
}
#define CP_ASYNC16(dst, src) \
    asm volatile("cp.async.cg.shared.global [%0], [%1], 16;\n" :: "r"(dst), "l"(src))
#define CP_COMMIT() asm volatile("cp.async.commit_group;\n" ::: "memory")
#define CP_WAIT0()  asm volatile("cp.async.wait_group 0;\n" ::: "memory")

// ---------------------------------------------------------------------------
// fp16 tensor-core GEMM (verified in R5): C = A[M,K] @ B[N,K]^T
// ---------------------------------------------------------------------------
__global__ void __launch_bounds__(256, 2) gemm_mma(const __half* __restrict__ A,
                                                   const __half* __restrict__ B,
                                                   float* __restrict__ C,
                                                   int N, int K)
{
    __shared__ __half As[2][5120];
    __shared__ __half Bs[2][5120];
    const int tid = threadIdx.x;
    const int w = tid >> 5, l = tid & 31;
    const int brow = blockIdx.y * 128, bcol = blockIdx.x * 128;
    const int wm = (w >> 2) * 64, wn = (w & 3) * 32;
    const uint32_t sa0 = smem_u32(As), sb0 = smem_u32(Bs);
    const int NIT = K >> 5;

    float acc[4][4][4];
#pragma unroll
    for (int a = 0; a < 4; a++)
#pragma unroll
        for (int b2 = 0; b2 < 4; b2++)
#pragma unroll
            for (int c = 0; c < 4; c++) acc[a][b2][c] = 0.f;

    const int lr0 = tid >> 2, lkc = tid & 3;
    const __half* Ag = A + (size_t)brow * K;
    const __half* Bg = B + (size_t)bcol * K;

    auto LOAD = [&](int buf, int k0) {
#pragma unroll
        for (int j = 0; j < 2; j++) {
            int r = lr0 + j * 64;
            uint32_t so = (uint32_t)(buf * 5120 + r * 40 + lkc * 8) * 2;
            CP_ASYNC16(sa0 + so, Ag + (size_t)r * K + k0 + lkc * 8);
            CP_ASYNC16(sb0 + so, Bg + (size_t)r * K + k0 + lkc * 8);
        }
        CP_COMMIT();
    };

    LOAD(0, 0);

    for (int i = 0; i < NIT; i++) {
        const int p = i & 1;
        if (i + 1 < NIT) {
            LOAD(p ^ 1, (i + 1) * 32);
            asm volatile("cp.async.wait_group 1;\n" ::: "memory");
        } else {
            CP_WAIT0();
        }
        __syncthreads();

        uint32_t bfr[4][4];
#pragma unroll
        for (int nf = 0; nf < 4; nf++)
            ldsm_x4(bfr[nf], sb0 + (uint32_t)(p * 5120 +
                    (wn + nf * 8 + (l & 7)) * 40 + (l >> 3) * 8) * 2);

#pragma unroll
        for (int s = 0; s < 2; s++) {
            uint32_t afr[4][4];
#pragma unroll
            for (int mf = 0; mf < 4; mf++) {
                int row = wm + mf * 16 + ((l >> 3) & 1) * 8 + (l & 7);
                int chunk = 2 * s + (l >> 4);
                ldsm_x4(afr[mf], sa0 + (uint32_t)(p * 5120 + row * 40 + chunk * 8) * 2);
            }
#pragma unroll
            for (int mf = 0; mf < 4; mf++)
#pragma unroll
                for (int nf = 0; nf < 4; nf++)
                    mma16816(acc[mf][nf], afr[mf], bfr[nf][2 * s], bfr[nf][2 * s + 1]);
        }
        __syncthreads();
    }

#pragma unroll
    for (int mf = 0; mf < 4; mf++) {
        int r0 = brow + wm + mf * 16 + (l >> 2);
#pragma unroll
        for (int nf = 0; nf < 4; nf++) {
            int c = bcol + wn + nf * 8 + (l & 3) * 2;
            *(float2*)(C + (size_t)r0 * N + c) = make_float2(acc[mf][nf][0], acc[mf][nf][1]);
            *(float2*)(C + (size_t)(r0 + 8) * N + c) = make_float2(acc[mf][nf][2], acc[mf][nf][3]);
        }
    }
}

// ---------------------------------------------------------------------------
// Converts
// ---------------------------------------------------------------------------
__global__ void conv_half4(const float* __restrict__ s, __half* __restrict__ d)
{
    int i = blockIdx.x * blockDim.x + threadIdx.x;
    float4 v = ((const float4*)s)[i];
    ((__half2*)d)[2 * i]     = __floats2half2_rn(v.x, v.y);
    ((__half2*)d)[2 * i + 1] = __floats2half2_rn(v.z, v.w);
}

__global__ void convT_half(const float* __restrict__ W,
                           __half* __restrict__ dst, int Ncols)
{
    __shared__ float t[32][33];
    int k0 = blockIdx.y * 32, n0 = blockIdx.x * 32;
    int tx = threadIdx.x, ty = threadIdx.y;
#pragma unroll
    for (int r = 0; r < 32; r += 8)
        t[ty + r][tx] = W[(size_t)(k0 + ty + r) * Ncols + n0 + tx];
    __syncthreads();
#pragma unroll
    for (int r = 0; r < 32; r += 8)
        dst[(size_t)(n0 + ty + r) * D_MODEL + k0 + tx] = __float2half(t[tx][ty + r]);
}

// RoPE on Q/K reading fp32 g_qkv, writing fp16 head-major Qh/Kh
__global__ void rope_conv(const float* __restrict__ sinp,
                          const float* __restrict__ cosp)
{
    int i = blockIdx.x * blockDim.x + threadIdx.x;   // M_TOT*20*64
    int d  = i & 63;
    int hh = (i >> 6) % 20;
    int m  = i / (64 * 20);
    int t  = m & (SEQ - 1);
    int b  = m >> 11;
    int col = (hh < 16) ? hh * 128 : D_MODEL + (hh - 16) * 128;
    float s = sinp[t * 64 + d];
    float c = cosp[t * 64 + d];
    const float* p = g_qkv + (size_t)m * QKV_N + col;
    float x1 = p[d], x2 = p[d + 64];
    float y1 = x1 * c - x2 * s;
    float y2 = x2 * c + x1 * s;
    __half* dst = (hh < 16)
        ? g_Qh + (((size_t)(b * 16 + hh)) * SEQ + t) * HEAD_DIM
        : g_Kh + (((size_t)(b * 4 + (hh - 16))) * SEQ + t) * HEAD_DIM;
    dst[d]      = __float2half(y1);
    dst[d + 64] = __float2half(y2);
}

// V transpose: g_qkv V cols -> g_Vt[b*4+g][d][s] fp16
__global__ void vt_conv()
{
    __shared__ float t[32][33];
    int n0 = blockIdx.x * 32;        // d
    int k0 = blockIdx.y * 32;        // s
    int z  = blockIdx.z;             // b*4+g
    int b = z >> 2, g = z & 3;
    int tx = threadIdx.x, ty = threadIdx.y;
#pragma unroll
    for (int r = 0; r < 32; r += 8)
        t[ty + r][tx] = g_qkv[(size_t)(b * SEQ + k0 + ty + r) * QKV_N +
                              D_MODEL + KV_DIM + g * 128 + n0 + tx];
    __syncthreads();
#pragma unroll
    for (int r = 0; r < 32; r += 8)
        g_Vt[((size_t)z * HEAD_DIM + n0 + ty + r) * SEQ + k0 + tx] =
            __float2half(t[tx][ty + r]);
}

// ---------------------------------------------------------------------------
// Tensor-core flash attention. Block: (qt, h, b); 256 threads (8 warps).
// QK: warp tile m16 x n32; PV: warp tile m16 x n64. fp32 accum, fp16 operands.
// ---------------------------------------------------------------------------
// smem byte offsets
#define AS_QS   0                      // 64 x 136 half  = 17408
#define AS_KS   17408                  // 64 x 136 half  = 17408
#define AS_VT   34816                  // 128 x 72 half  = 18432
#define AS_SS   53248                  // 64 x 67 float  = 17152
#define AS_PS   70400                  // 64 x 72 half   = 9216
#define AS_RM   79616
#define AS_RL   79872
#define AS_CO   80128
#define AS_QD   80384
#define AS_KD   80640
#define ATT_SMEM 80896

__global__ void __launch_bounds__(256) attn_mma(const int* __restrict__ doc_ids)
{
    extern __shared__ char smem[];
    const uint32_t sb = smem_u32(smem);
    const uint32_t uQ = sb + AS_QS, uK = sb + AS_KS, uV = sb + AS_VT, uP = sb + AS_PS;
    float* Ss   = (float*)(smem + AS_SS);
    __half* Ps  = (__half*)(smem + AS_PS);
    float* rowm = (float*)(smem + AS_RM);
    float* rowl = (float*)(smem + AS_RL);
    float* corr = (float*)(smem + AS_CO);
    int* qdoc   = (int*)(smem + AS_QD);
    int* kdoc   = (int*)(smem + AS_KD);

    const int qt = blockIdx.x, h = blockIdx.y, b = blockIdx.z;
    const int g = h >> 2;
    const int tid = threadIdx.x, w = tid >> 5, l = tid & 31;
    const int wm = (w >> 1) * 16, wnq = (w & 1) * 32, wnv = (w & 1) * 64;
    const int t0 = qt * 64;
    const float scale = 0.08838834764831845f;

    // load Q tile (64 x 128) -> stride 136
    const __half* qsrc = g_Qh + (((size_t)(b * 16 + h)) * SEQ + t0) * HEAD_DIM;
#pragma unroll
    for (int j = 0; j < 4; j++) {
        int idx = tid + j * 256;
        int r = idx >> 4, c = idx & 15;
        CP_ASYNC16(uQ + (uint32_t)(r * 136 + c * 8) * 2, qsrc + r * 128 + c * 8);
    }
    CP_COMMIT();

    if (tid < 64) {
        qdoc[tid] = doc_ids[b * SEQ + t0 + tid];
        rowm[tid] = -1e30f;
        rowl[tid] = 0.f;
    }
    float acc2[8][4];
#pragma unroll
    for (int nf = 0; nf < 8; nf++)
#pragma unroll
        for (int q = 0; q < 4; q++) acc2[nf][q] = 0.f;

    CP_WAIT0();
    __syncthreads();
    const int dq_min = qdoc[0];
    const int r0 = wm + (l >> 2);

    for (int kt = 0; kt <= qt; kt++) {
        if (tid < 64) kdoc[tid] = doc_ids[b * SEQ + kt * 64 + tid];
        __syncthreads();
        bool skip = (kdoc[63] < dq_min);
        __syncthreads();                 // protect kdoc[63] read vs next write
        if (skip) continue;

        // load K (64x128 -> stride 136) and Vt (128x64 -> stride 72)
        const __half* ksrc = g_Kh + (((size_t)(b * 4 + g)) * SEQ + kt * 64) * HEAD_DIM;
        const __half* vsrc = g_Vt + ((size_t)(b * 4 + g) * HEAD_DIM) * SEQ + kt * 64;
#pragma unroll
        for (int j = 0; j < 4; j++) {
            int idx = tid + j * 256;
            int r = idx >> 4, c = idx & 15;
            CP_ASYNC16(uK + (uint32_t)(r * 136 + c * 8) * 2, ksrc + r * 128 + c * 8);
        }
#pragma unroll
        for (int j = 0; j < 4; j++) {
            int idx = tid + j * 256;
            int r = idx >> 3, c = idx & 7;
            CP_ASYNC16(uV + (uint32_t)(r * 72 + c * 8) * 2, vsrc + (size_t)r * SEQ + c * 8);
        }
        CP_COMMIT();
        CP_WAIT0();
        __syncthreads();

        // ---- QK^T -> s4 ----
        float s4[4][4];
#pragma unroll
        for (int nf = 0; nf < 4; nf++)
#pragma unroll
            for (int q = 0; q < 4; q++) s4[nf][q] = 0.f;

#pragma unroll
        for (int kb = 0; kb < 4; kb++) {
            uint32_t afr[2][4];
#pragma unroll
            for (int s = 0; s < 2; s++)
                ldsm_x4(afr[s], uQ + (uint32_t)((wm + ((l >> 3) & 1) * 8 + (l & 7)) * 136 +
                        (kb * 4 + 2 * s + (l >> 4)) * 8) * 2);
#pragma unroll
            for (int nf = 0; nf < 4; nf++) {
                uint32_t bfr[4];
                ldsm_x4(bfr, uK + (uint32_t)((wnq + nf * 8 + (l & 7)) * 136 +
                        (kb * 4 + (l >> 3)) * 8) * 2);
                mma16816(s4[nf], afr[0], bfr[0], bfr[1]);
                mma16816(s4[nf], afr[1], bfr[2], bfr[3]);
            }
        }

        // ---- scale + mask -> Ss ----
        {
            int qi0 = t0 + r0, qi8 = qi0 + 8;
            int qd0 = qdoc[r0], qd8 = qdoc[r0 + 8];
#pragma unroll
            for (int nf = 0; nf < 4; nf++) {
                int c = wnq + nf * 8 + (l & 3) * 2;
                int kj = kt * 64 + c;
                Ss[r0 * 67 + c] =
                    (kj > qi0 || qd0 != kdoc[c]) ? -1e30f : s4[nf][0] * scale;
                Ss[r0 * 67 + c + 1] =
                    (kj + 1 > qi0 || qd0 != kdoc[c + 1]) ? -1e30f : s4[nf][1] * scale;
                Ss[(r0 + 8) * 67 + c] =
                    (kj > qi8 || qd8 != kdoc[c]) ? -1e30f : s4[nf][2] * scale;
                Ss[(r0 + 8) * 67 + c + 1] =
                    (kj + 1 > qi8 || qd8 != kdoc[c + 1]) ? -1e30f : s4[nf][3] * scale;
            }
        }
        __syncthreads();

        // ---- online softmax, P (fp16) ----
        if (tid < 64) {
            int r = tid;
            float mold = rowm[r], mx = mold;
#pragma unroll 8
            for (int c = 0; c < 64; c++) mx = fmaxf(mx, Ss[r * 67 + c]);
            float cf = __expf(mold - mx);
            float lsum = rowl[r] * cf;
#pragma unroll 8
            for (int c = 0; c < 64; c++) {
                float sv = Ss[r * 67 + c];
                float e = (sv > -1e29f) ? __expf(sv - mx) : 0.f;
                Ps[r * 72 + c] = __float2half(e);
                lsum += e;
            }
            rowm[r] = mx;
            rowl[r] = lsum;
            corr[r] = cf;
        }
        __syncthreads();

        // ---- rescale accumulators ----
        {
            float cf0 = corr[r0], cf8 = corr[r0 + 8];
#pragma unroll
            for (int nf = 0; nf < 8; nf++) {
                acc2[nf][0] *= cf0; acc2[nf][1] *= cf0;
                acc2[nf][2] *= cf8; acc2[nf][3] *= cf8;
            }
        }

        // ---- PV: acc2 += P[64x64] @ Vt^T ----
#pragma unroll
        for (int kb = 0; kb < 2; kb++) {
            uint32_t afr[2][4];
#pragma unroll
            for (int s = 0; s < 2; s++)
                ldsm_x4(afr[s], uP + (uint32_t)((wm + ((l >> 3) & 1) * 8 + (l & 7)) * 72 +
                        (kb * 4 + 2 * s + (l >> 4)) * 8) * 2);
#pragma unroll
            for (int nf = 0; nf < 8; nf++) {
                uint32_t bfr[4];
                ldsm_x4(bfr, uV + (uint32_t)((wnv + nf * 8 + (l & 7)) * 72 +
                        (kb * 4 + (l >> 3)) * 8) * 2);
                mma16816(acc2[nf], afr[0], bfr[0], bfr[1]);
                mma16816(acc2[nf], afr[1], bfr[2], bfr[3]);
            }
        }
        __syncthreads();   // protect smem tiles before next iteration
    }

    // ---- epilogue: /l, fp16 -> g_Aatt ----
    {
        float inv0 = 1.f / rowl[r0], inv8 = 1.f / rowl[r0 + 8];
        size_t m0 = (size_t)(b * SEQ + t0 + r0) * D_MODEL;
        size_t m8 = (size_t)(b * SEQ + t0 + r0 + 8) * D_MODEL;
#pragma unroll
        for (int nf = 0; nf < 8; nf++) {
            int c = h * 128 + wnv + nf * 8 + (l & 3) * 2;
            *(__half2*)(g_Aatt + m0 + c) =
                __floats2half2_rn(acc2[nf][0] * inv0, acc2[nf][1] * inv0);
            *(__half2*)(g_Aatt + m8 + c) =
                __floats2half2_rn(acc2[nf][2] * inv8, acc2[nf][3] * inv8);
        }
    }
}

// ---------------------------------------------------------------------------
extern "C" void kernel_launch(void* const* d_in, const int* in_sizes, int n_in,
                              void* d_out, int out_size)
{
    const float* x    = (const float*)d_in[0];
    const float* sinp = (const float*)d_in[1];
    const float* cosp = (const float*)d_in[2];
    const int*   doc  = (const int*)d_in[3];
    const float* Wqkv = (const float*)d_in[4];
    const float* Wo   = (const float*)d_in[5];
    float* out = (float*)d_out;

    float* qkv_ptr;
    __half *ax, *aatt, *bqkv, *bo;
    cudaGetSymbolAddress((void**)&qkv_ptr, g_qkv);
    cudaGetSymbolAddress((void**)&ax,   g_Ax);
    cudaGetSymbolAddress((void**)&aatt, g_Aatt);
    cudaGetSymbolAddress((void**)&bqkv, g_Bqkv);
    cudaGetSymbolAddress((void**)&bo,   g_Bo);

    cudaFuncSetAttribute(attn_mma, cudaFuncAttributeMaxDynamicSharedMemorySize,
                         ATT_SMEM);

    // 1) fp16 conversions for QKV GEMM
    conv_half4<<<(M_TOT * D_MODEL / 4) / 256, 256>>>(x, ax);
    convT_half<<<dim3(QKV_N / 32, D_MODEL / 32), dim3(32, 8)>>>(Wqkv, bqkv, QKV_N);

    // 2) QKV projection (fp16 mma)
    gemm_mma<<<dim3(QKV_N / 128, M_TOT / 128), 256>>>(ax, bqkv, qkv_ptr, QKV_N, D_MODEL);

    // 3) RoPE + fp16 head-major Q/K; V transpose
    rope_conv<<<(M_TOT * 20 * 64) / 256, 256>>>(sinp, cosp);
    vt_conv<<<dim3(HEAD_DIM / 32, SEQ / 32, BATCHN * 4), dim3(32, 8)>>>();

    // 4) Tensor-core flash attention
    attn_mma<<<dim3(SEQ / 64, NUM_HEADS, BATCHN), 256, ATT_SMEM>>>(doc);

    // 5) Output projection
    convT_half<<<dim3(D_MODEL / 32, D_MODEL / 32), dim3(32, 8)>>>(Wo, bo, D_MODEL);
    gemm_mma<<<dim3(D_MODEL / 128, M_TOT / 128), 256>>>(aatt, bo, out, D_MODEL, D_MODEL);
}

// round 8
// speedup vs baseline: 5.9180x; 1.2492x over previous
#include <cuda_runtime.h>
#include <cuda_fp16.h>
#include <cstdint>
#include <math.h>

#define D_MODEL   2048
#define NUM_HEADS 16
#define HEAD_DIM  128
#define KV_DIM    512
#define QKV_N     3072
#define BATCHN    2
#define SEQ       2048
#define M_TOT     4096

// ---------------------------------------------------------------------------
// Scratch (__device__ globals; allocation-free rule)
// ---------------------------------------------------------------------------
__device__ float g_qkv[(size_t)M_TOT * QKV_N];
__device__ __align__(16) __half g_Ax[(size_t)M_TOT * D_MODEL];
__device__ __align__(16) __half g_Aatt[(size_t)M_TOT * D_MODEL];
__device__ __align__(16) __half g_Bqkv[(size_t)QKV_N * D_MODEL];
__device__ __align__(16) __half g_Bo[(size_t)D_MODEL * D_MODEL];
__device__ __align__(16) __half g_Qh[(size_t)BATCHN * NUM_HEADS * SEQ * HEAD_DIM];
__device__ __align__(16) __half g_Kh[(size_t)BATCHN * 4 * SEQ * HEAD_DIM];
__device__ __align__(16) __half g_Vt[(size_t)BATCHN * 4 * HEAD_DIM * SEQ];

__device__ __forceinline__ uint32_t smem_u32(const void* p) {
    uint32_t a;
    asm("{ .reg .u64 t; cvta.to.shared.u64 t, %1; cvt.u32.u64 %0, t; }" : "=r"(a) : "l"(p));
    return a;
}
__device__ __forceinline__ void ldsm_x4(uint32_t* r, uint32_t addr) {
    asm volatile("ldmatrix.sync.aligned.m8n8.x4.shared.b16 {%0,%1,%2,%3}, [%4];"
                 : "=r"(r[0]), "=r"(r[1]), "=r"(r[2]), "=r"(r[3]) : "r"(addr) : "memory");
}
__device__ __forceinline__ void mma16816(float* c, const uint32_t* a,
                                         uint32_t b0, uint32_t b1) {
    asm volatile("mma.sync.aligned.m16n8k16.row.col.f32.f16.f16.f32 "
                 "{%0,%1,%2,%3},{%4,%5,%6,%7},{%8,%9},{%0,%1,%2,%3};"
                 : "+f"(c[0]), "+f"(c[1]), "+f"(c[2]), "+f"(c[3])
                 : "r"(a[0]), "r"(a[1]), "r"(a[2]), "r"(a[3]), "r"(b0), "r"(b1));
}
__device__ __forceinline__ uint32_t packh2(float a, float b) {
    __half2 h = __floats2half2_rn(a, b);
    return *(uint32_t*)&h;
}
#define CP_ASYNC16(dst, src) \
    asm volatile("cp.async.cg.shared.global [%0], [%1], 16;\n" :: "r"(dst), "l"(src))
#define CP_COMMIT() asm volatile("cp.async.commit_group;\n" ::: "memory")
#define CP_WAIT0()  asm volatile("cp.async.wait_group 0;\n" ::: "memory")
#define CP_WAIT1()  asm volatile("cp.async.wait_group 1;\n" ::: "memory")

// ---------------------------------------------------------------------------
// fp16 tensor-core GEMM, 3-stage cp.async pipeline: C = A[M,K] @ B[N,K]^T
// ---------------------------------------------------------------------------
#define GSM_BYTES (6 * 5120 * 2)   // 3 A-bufs + 3 B-bufs, 5120 halves each

__global__ void __launch_bounds__(256, 2) gemm_mma(const __half* __restrict__ A,
                                                   const __half* __restrict__ B,
                                                   float* __restrict__ C,
                                                   int N, int K)
{
    extern __shared__ __half gsm[];
    __half* As = gsm;                 // [3][5120]
    __half* Bs = gsm + 3 * 5120;      // [3][5120]
    const int tid = threadIdx.x;
    const int w = tid >> 5, l = tid & 31;
    const int brow = blockIdx.y * 128, bcol = blockIdx.x * 128;
    const int wm = (w >> 2) * 64, wn = (w & 3) * 32;
    const uint32_t sa0 = smem_u32(As), sb0 = smem_u32(Bs);
    const int NIT = K >> 5;

    float acc[4][4][4];
#pragma unroll
    for (int a = 0; a < 4; a++)
#pragma unroll
        for (int b2 = 0; b2 < 4; b2++)
#pragma unroll
            for (int c = 0; c < 4; c++) acc[a][b2][c] = 0.f;

    const int lr0 = tid >> 2, lkc = tid & 3;
    const __half* Ag = A + (size_t)brow * K;
    const __half* Bg = B + (size_t)bcol * K;

    auto LOAD = [&](int buf, int k0) {
#pragma unroll
        for (int j = 0; j < 2; j++) {
            int r = lr0 + j * 64;
            uint32_t so = (uint32_t)(buf * 5120 + r * 40 + lkc * 8) * 2;
            CP_ASYNC16(sa0 + so, Ag + (size_t)r * K + k0 + lkc * 8);
            CP_ASYNC16(sb0 + so, Bg + (size_t)r * K + k0 + lkc * 8);
        }
        CP_COMMIT();
    };

    LOAD(0, 0);
    LOAD(1, 32);

    for (int i = 0; i < NIT; i++) {
        const int p = i % 3;
        if (i == NIT - 1) { CP_WAIT0(); } else { CP_WAIT1(); }
        __syncthreads();
        if (i + 2 < NIT) LOAD((i + 2) % 3, (i + 2) * 32);

        uint32_t bfr[4][4];
#pragma unroll
        for (int nf = 0; nf < 4; nf++)
            ldsm_x4(bfr[nf], sb0 + (uint32_t)(p * 5120 +
                    (wn + nf * 8 + (l & 7)) * 40 + (l >> 3) * 8) * 2);

#pragma unroll
        for (int s = 0; s < 2; s++) {
            uint32_t afr[4][4];
#pragma unroll
            for (int mf = 0; mf < 4; mf++) {
                int row = wm + mf * 16 + ((l >> 3) & 1) * 8 + (l & 7);
                int chunk = 2 * s + (l >> 4);
                ldsm_x4(afr[mf], sa0 + (uint32_t)(p * 5120 + row * 40 + chunk * 8) * 2);
            }
#pragma unroll
            for (int mf = 0; mf < 4; mf++)
#pragma unroll
                for (int nf = 0; nf < 4; nf++)
                    mma16816(acc[mf][nf], afr[mf], bfr[nf][2 * s], bfr[nf][2 * s + 1]);
        }
        // no trailing barrier: next iteration's wait+sync protects buffers
    }

#pragma unroll
    for (int mf = 0; mf < 4; mf++) {
        int r0 = brow + wm + mf * 16 + (l >> 2);
#pragma unroll
        for (int nf = 0; nf < 4; nf++) {
            int c = bcol + wn + nf * 8 + (l & 3) * 2;
            *(float2*)(C + (size_t)r0 * N + c) = make_float2(acc[mf][nf][0], acc[mf][nf][1]);
            *(float2*)(C + (size_t)(r0 + 8) * N + c) = make_float2(acc[mf][nf][2], acc[mf][nf][3]);
        }
    }
}

// ---------------------------------------------------------------------------
// Converts (unchanged, verified)
// ---------------------------------------------------------------------------
__global__ void conv_half4(const float* __restrict__ s, __half* __restrict__ d)
{
    int i = blockIdx.x * blockDim.x + threadIdx.x;
    float4 v = ((const float4*)s)[i];
    ((__half2*)d)[2 * i]     = __floats2half2_rn(v.x, v.y);
    ((__half2*)d)[2 * i + 1] = __floats2half2_rn(v.z, v.w);
}

__global__ void convT_half(const float* __restrict__ W,
                           __half* __restrict__ dst, int Ncols)
{
    __shared__ float t[32][33];
    int k0 = blockIdx.y * 32, n0 = blockIdx.x * 32;
    int tx = threadIdx.x, ty = threadIdx.y;
#pragma unroll
    for (int r = 0; r < 32; r += 8)
        t[ty + r][tx] = W[(size_t)(k0 + ty + r) * Ncols + n0 + tx];
    __syncthreads();
#pragma unroll
    for (int r = 0; r < 32; r += 8)
        dst[(size_t)(n0 + ty + r) * D_MODEL + k0 + tx] = __float2half(t[tx][ty + r]);
}

__global__ void rope_conv(const float* __restrict__ sinp,
                          const float* __restrict__ cosp)
{
    int i = blockIdx.x * blockDim.x + threadIdx.x;
    int d  = i & 63;
    int hh = (i >> 6) % 20;
    int m  = i / (64 * 20);
    int t  = m & (SEQ - 1);
    int b  = m >> 11;
    int col = (hh < 16) ? hh * 128 : D_MODEL + (hh - 16) * 128;
    float s = sinp[t * 64 + d];
    float c = cosp[t * 64 + d];
    const float* p = g_qkv + (size_t)m * QKV_N + col;
    float x1 = p[d], x2 = p[d + 64];
    float y1 = x1 * c - x2 * s;
    float y2 = x2 * c + x1 * s;
    __half* dst = (hh < 16)
        ? g_Qh + (((size_t)(b * 16 + hh)) * SEQ + t) * HEAD_DIM
        : g_Kh + (((size_t)(b * 4 + (hh - 16))) * SEQ + t) * HEAD_DIM;
    dst[d]      = __float2half(y1);
    dst[d + 64] = __float2half(y2);
}

__global__ void vt_conv()
{
    __shared__ float t[32][33];
    int n0 = blockIdx.x * 32;
    int k0 = blockIdx.y * 32;
    int z  = blockIdx.z;
    int b = z >> 2, g = z & 3;
    int tx = threadIdx.x, ty = threadIdx.y;
#pragma unroll
    for (int r = 0; r < 32; r += 8)
        t[ty + r][tx] = g_qkv[(size_t)(b * SEQ + k0 + ty + r) * QKV_N +
                              D_MODEL + KV_DIM + g * 128 + n0 + tx];
    __syncthreads();
#pragma unroll
    for (int r = 0; r < 32; r += 8)
        g_Vt[((size_t)z * HEAD_DIM + n0 + ty + r) * SEQ + k0 + tx] =
            __float2half(t[tx][ty + r]);
}

// ---------------------------------------------------------------------------
// FA-2-style tensor-core attention. TQ=128 queries/block, 8 warps.
// Warp w owns query rows [w*16, w*16+16), ALL 64 key cols of the k-tile.
// Softmax fully in registers (quad shfl); P C-frags repack to PV A-frags.
// K/V/kdoc double-buffered; one barrier per k-tile.
// ---------------------------------------------------------------------------
#define BS_Q   0                       // 128 x 136 half = 34816
#define BS_K   34816                   // 2 x (64 x 136) half
#define BS_V   69632                   // 2 x (128 x 72) half
#define BS_KD  106496                  // 2 x 64 int
#define ATT_SMEM 107008

__global__ void __launch_bounds__(256, 1) attn_mma(const int* __restrict__ doc_ids)
{
    extern __shared__ char smem[];
    const uint32_t sb = smem_u32(smem);
    const uint32_t uQ = sb + BS_Q;

    const int qt = (int)(gridDim.x - 1) - (int)blockIdx.x;   // heavy blocks first
    const int h = blockIdx.y, b = blockIdx.z;
    const int g = h >> 2;
    const int tid = threadIdx.x, w = tid >> 5, l = tid & 31;
    const int wm = w * 16;
    const int t0 = qt * 128;
    const float scale = 0.08838834764831845f;

    // Q tile load: 128 x 128 halves, stride 136
    const __half* qsrc = g_Qh + (((size_t)(b * 16 + h)) * SEQ + t0) * HEAD_DIM;
#pragma unroll
    for (int j = 0; j < 8; j++) {
        int idx = tid + j * 256;
        int r = idx >> 4, c = idx & 15;
        CP_ASYNC16(uQ + (uint32_t)(r * 136 + c * 8) * 2, qsrc + r * 128 + c * 8);
    }
    CP_COMMIT();

    const int r0 = wm + (l >> 2);
    const int qi0 = t0 + r0, qi8 = qi0 + 8;
    const int dbase = b * SEQ;
    const int qd0 = doc_ids[dbase + qi0];
    const int qd8 = doc_ids[dbase + qi8];
    const int dq_min = doc_ids[dbase + t0];

    float rowm0 = -1e30f, rowm8 = -1e30f, rowl0 = 0.f, rowl8 = 0.f;
    float acc[16][4];
#pragma unroll
    for (int nf = 0; nf < 16; nf++)
#pragma unroll
        for (int q = 0; q < 4; q++) acc[nf][q] = 0.f;

    const __half* kbase = g_Kh + ((size_t)(b * 4 + g)) * SEQ * HEAD_DIM;
    const __half* vbase = g_Vt + ((size_t)(b * 4 + g) * HEAD_DIM) * SEQ;

    auto load_tile = [&](int t, int buf) {
        const __half* ks = kbase + (size_t)t * 64 * HEAD_DIM;
        const __half* vs = vbase + t * 64;
        uint32_t uk = sb + BS_K + buf * 17408;
        uint32_t uv = sb + BS_V + buf * 18432;
#pragma unroll
        for (int j = 0; j < 4; j++) {
            int idx = tid + j * 256;
            int r = idx >> 4, c = idx & 15;
            CP_ASYNC16(uk + (uint32_t)(r * 136 + c * 8) * 2, ks + r * 128 + c * 8);
        }
#pragma unroll
        for (int j = 0; j < 4; j++) {
            int idx = tid + j * 256;
            int r = idx >> 3, c = idx & 7;
            CP_ASYNC16(uv + (uint32_t)(r * 72 + c * 8) * 2, vs + (size_t)r * SEQ + c * 8);
        }
        if (tid < 64)
            ((int*)(smem + BS_KD + buf * 256))[tid] = doc_ids[dbase + t * 64 + tid];
    };

    const int ktmax = 2 * qt + 1;
    int kt = 0;
    while (kt <= ktmax && doc_ids[dbase + kt * 64 + 63] < dq_min) kt++;
    // tile containing t0 is never skipped, so kt <= ktmax here.

    int p = 0;
    load_tile(kt, 0);
    CP_COMMIT();
    CP_WAIT0();
    __syncthreads();

    while (true) {
        int ktn = kt + 1;
        while (ktn <= ktmax && doc_ids[dbase + ktn * 64 + 63] < dq_min) ktn++;
        const bool havenext = (ktn <= ktmax);
        if (havenext) { load_tile(ktn, p ^ 1); CP_COMMIT(); }

        const uint32_t uk = sb + BS_K + p * 17408;
        const uint32_t uv = sb + BS_V + p * 18432;
        const int* kd = (const int*)(smem + BS_KD + p * 256);

        // ---- QK^T: 16 rows x 64 cols per warp ----
        float e[8][4];
#pragma unroll
        for (int nf = 0; nf < 8; nf++)
#pragma unroll
            for (int q = 0; q < 4; q++) e[nf][q] = 0.f;

#pragma unroll
        for (int kb = 0; kb < 4; kb++) {
            uint32_t afr[2][4];
#pragma unroll
            for (int s = 0; s < 2; s++)
                ldsm_x4(afr[s], uQ + (uint32_t)((wm + ((l >> 3) & 1) * 8 + (l & 7)) * 136 +
                        (kb * 4 + 2 * s + (l >> 4)) * 8) * 2);
#pragma unroll
            for (int nf = 0; nf < 8; nf++) {
                uint32_t bfr[4];
                ldsm_x4(bfr, uk + (uint32_t)((nf * 8 + (l & 7)) * 136 +
                        (kb * 4 + (l >> 3)) * 8) * 2);
                mma16816(e[nf], afr[0], bfr[0], bfr[1]);
                mma16816(e[nf], afr[1], bfr[2], bfr[3]);
            }
        }

        // ---- scale + mask (in registers) ----
        const int kcol0 = kt * 64;
#pragma unroll
        for (int nf = 0; nf < 8; nf++) {
            int c = nf * 8 + (l & 3) * 2;
            int kj = kcol0 + c;
            int kdc = kd[c], kdc1 = kd[c + 1];
            e[nf][0] = (kj     > qi0 || qd0 != kdc ) ? -1e30f : e[nf][0] * scale;
            e[nf][1] = (kj + 1 > qi0 || qd0 != kdc1) ? -1e30f : e[nf][1] * scale;
            e[nf][2] = (kj     > qi8 || qd8 != kdc ) ? -1e30f : e[nf][2] * scale;
            e[nf][3] = (kj + 1 > qi8 || qd8 != kdc1) ? -1e30f : e[nf][3] * scale;
        }

        // ---- online softmax in registers (quad shuffle) ----
        float mx0 = rowm0, mx8 = rowm8;
#pragma unroll
        for (int nf = 0; nf < 8; nf++) {
            mx0 = fmaxf(mx0, fmaxf(e[nf][0], e[nf][1]));
            mx8 = fmaxf(mx8, fmaxf(e[nf][2], e[nf][3]));
        }
        mx0 = fmaxf(mx0, __shfl_xor_sync(0xffffffffu, mx0, 1));
        mx0 = fmaxf(mx0, __shfl_xor_sync(0xffffffffu, mx0, 2));
        mx8 = fmaxf(mx8, __shfl_xor_sync(0xffffffffu, mx8, 1));
        mx8 = fmaxf(mx8, __shfl_xor_sync(0xffffffffu, mx8, 2));

        float cf0 = __expf(rowm0 - mx0);
        float cf8 = __expf(rowm8 - mx8);
        float ts0 = 0.f, ts8 = 0.f;
#pragma unroll
        for (int nf = 0; nf < 8; nf++) {
            e[nf][0] = (e[nf][0] > -1e29f) ? __expf(e[nf][0] - mx0) : 0.f;
            e[nf][1] = (e[nf][1] > -1e29f) ? __expf(e[nf][1] - mx0) : 0.f;
            e[nf][2] = (e[nf][2] > -1e29f) ? __expf(e[nf][2] - mx8) : 0.f;
            e[nf][3] = (e[nf][3] > -1e29f) ? __expf(e[nf][3] - mx8) : 0.f;
            ts0 += e[nf][0] + e[nf][1];
            ts8 += e[nf][2] + e[nf][3];
        }
        ts0 += __shfl_xor_sync(0xffffffffu, ts0, 1);
        ts0 += __shfl_xor_sync(0xffffffffu, ts0, 2);
        ts8 += __shfl_xor_sync(0xffffffffu, ts8, 1);
        ts8 += __shfl_xor_sync(0xffffffffu, ts8, 2);
        rowm0 = mx0; rowm8 = mx8;
        rowl0 = rowl0 * cf0 + ts0;
        rowl8 = rowl8 * cf8 + ts8;

        // ---- rescale accumulators ----
#pragma unroll
        for (int nf = 0; nf < 16; nf++) {
            acc[nf][0] *= cf0; acc[nf][1] *= cf0;
            acc[nf][2] *= cf8; acc[nf][3] *= cf8;
        }

        // ---- P C-frags -> PV A-frags (register repack), then PV ----
        uint32_t pa[4][4];
#pragma unroll
        for (int j = 0; j < 4; j++) {
            pa[j][0] = packh2(e[2 * j][0],     e[2 * j][1]);
            pa[j][1] = packh2(e[2 * j][2],     e[2 * j][3]);
            pa[j][2] = packh2(e[2 * j + 1][0], e[2 * j + 1][1]);
            pa[j][3] = packh2(e[2 * j + 1][2], e[2 * j + 1][3]);
        }
#pragma unroll
        for (int kb2 = 0; kb2 < 2; kb2++) {
#pragma unroll
            for (int nf = 0; nf < 16; nf++) {
                uint32_t bfr[4];
                ldsm_x4(bfr, uv + (uint32_t)((nf * 8 + (l & 7)) * 72 +
                        (kb2 * 4 + (l >> 3)) * 8) * 2);
                mma16816(acc[nf], pa[2 * kb2],     bfr[0], bfr[1]);
                mma16816(acc[nf], pa[2 * kb2 + 1], bfr[2], bfr[3]);
            }
        }

        if (!havenext) break;
        CP_WAIT0();
        __syncthreads();
        p ^= 1;
        kt = ktn;
    }

    // ---- epilogue: /l, fp16 -> g_Aatt ----
    {
        float inv0 = 1.f / rowl0, inv8 = 1.f / rowl8;
        size_t m0 = (size_t)(b * SEQ + qi0 - b * SEQ + t0 * 0 + qi0) * 0; // (unused)
        size_t row0 = (size_t)(dbase + qi0) * D_MODEL;
        size_t row8 = (size_t)(dbase + qi8) * D_MODEL;
        (void)m0;
#pragma unroll
        for (int nf = 0; nf < 16; nf++) {
            int c = h * 128 + nf * 8 + (l & 3) * 2;
            *(__half2*)(g_Aatt + row0 + c) =
                __floats2half2_rn(acc[nf][0] * inv0, acc[nf][1] * inv0);
            *(__half2*)(g_Aatt + row8 + c) =
                __floats2half2_rn(acc[nf][2] * inv8, acc[nf][3] * inv8);
        }
    }
}

// ---------------------------------------------------------------------------
extern "C" void kernel_launch(void* const* d_in, const int* in_sizes, int n_in,
                              void* d_out, int out_size)
{
    const float* x    = (const float*)d_in[0];
    const float* sinp = (const float*)d_in[1];
    const float* cosp = (const float*)d_in[2];
    const int*   doc  = (const int*)d_in[3];
    const float* Wqkv = (const float*)d_in[4];
    const float* Wo   = (const float*)d_in[5];
    float* out = (float*)d_out;

    float* qkv_ptr;
    __half *ax, *aatt, *bqkv, *bo;
    cudaGetSymbolAddress((void**)&qkv_ptr, g_qkv);
    cudaGetSymbolAddress((void**)&ax,   g_Ax);
    cudaGetSymbolAddress((void**)&aatt, g_Aatt);
    cudaGetSymbolAddress((void**)&bqkv, g_Bqkv);
    cudaGetSymbolAddress((void**)&bo,   g_Bo);

    cudaFuncSetAttribute(gemm_mma, cudaFuncAttributeMaxDynamicSharedMemorySize,
                         GSM_BYTES);
    cudaFuncSetAttribute(attn_mma, cudaFuncAttributeMaxDynamicSharedMemorySize,
                         ATT_SMEM);

    // 1) fp16 conversions
    conv_half4<<<(M_TOT * D_MODEL / 4) / 256, 256>>>(x, ax);
    convT_half<<<dim3(QKV_N / 32, D_MODEL / 32), dim3(32, 8)>>>(Wqkv, bqkv, QKV_N);

    // 2) QKV projection
    gemm_mma<<<dim3(QKV_N / 128, M_TOT / 128), 256, GSM_BYTES>>>(ax, bqkv, qkv_ptr,
                                                                 QKV_N, D_MODEL);

    // 3) RoPE + head-major fp16 Q/K; V transpose
    rope_conv<<<(M_TOT * 20 * 64) / 256, 256>>>(sinp, cosp);
    vt_conv<<<dim3(HEAD_DIM / 32, SEQ / 32, BATCHN * 4), dim3(32, 8)>>>();

    // 4) FA-2-style tensor-core attention (TQ=128)
    attn_mma<<<dim3(SEQ / 128, NUM_HEADS, BATCHN), 256, ATT_SMEM>>>(doc);

    // 5) Output projection
    convT_half<<<dim3(D_MODEL / 32, D_MODEL / 32), dim3(32, 8)>>>(Wo, bo, D_MODEL);
    gemm_mma<<<dim3(D_MODEL / 128, M_TOT / 128), 256, GSM_BYTES>>>(aatt, bo, out,
                                                                   D_MODEL, D_MODEL);
}